// round 4
// baseline (speedup 1.0000x reference)
#include <cuda_runtime.h>
#include <cuda_pipeline.h>

#define Bx 4
#define Nn 2048
#define Dd 512
#define Hh 8
#define NCH 32      // chunks of 64 node rows
#define ROWS 64
#define SUB 16
#define NSUB (ROWS / SUB)

// ---------------- device scratch ----------------
__device__ float g_u[Hh][Dd];
__device__ float g_ch[Hh];
__device__ float g_s0p[Hh][8];             // partial u.ct per 64-dim chunk
__device__ float g_pm[Bx][NCH][Hh];
__device__ float g_ps[Bx][NCH][Hh];
__device__ float g_zp[NCH][Bx][Hh][Dd];    // per-chunk unnormalized z
__device__ float g_w[Bx][Dd];              // Wv z + bv
__device__ float g_y[Bx][Dd];              // pre-LN y
__device__ unsigned g_cnt = 0;             // last-block ticket (reset each run)

__device__ __forceinline__ float warp_sum(float v) {
    #pragma unroll
    for (int o = 16; o; o >>= 1) v += __shfl_xor_sync(0xffffffffu, v, o);
    return v;
}
__device__ __forceinline__ float warp_max(float v) {
    #pragma unroll
    for (int o = 16; o; o >>= 1) v = fmaxf(v, __shfl_xor_sync(0xffffffffu, v, o));
    return v;
}
__device__ __forceinline__ float dot4(float4 a, float4 b) {
    return a.x * b.x + a.y * b.y + a.z * b.z + a.w * b.w;
}

// ============ k_prep: per (head, d-chunk): q0 slice (redundant), u, s0p, ch ============
// grid (Hh, 8), 512 threads
__global__ void k_prep(const float* __restrict__ Wq, const float* __restrict__ bq,
                       const float* __restrict__ Wk, const float* __restrict__ bk,
                       const float* __restrict__ ct) {
    const int h = blockIdx.x, dc = blockIdx.y;
    const int t = threadIdx.x, wid = t >> 5, lane = t & 31;
    __shared__ __align__(16) float cts[Dd];
    __shared__ float q0s[64];
    __shared__ float red8[8][64];
    __shared__ float red64[64];
    cts[t] = ct[t];
    __syncthreads();
    // q0 slice for head h: 16 warps x 4 rows
    {
        const float4* cv = (const float4*)cts;
        #pragma unroll
        for (int rr = 0; rr < 4; rr++) {
            const int i = wid + rr * 16;
            const float4* row = (const float4*)(Wq + (size_t)(h * 64 + i) * Dd);
            float s = 0.f;
            #pragma unroll
            for (int k = 0; k < 4; k++) s += dot4(row[lane + 32 * k], cv[lane + 32 * k]);
            s = warp_sum(s);
            if (lane == 0) q0s[i] = s + bq[h * 64 + i];
        }
    }
    __syncthreads();
    // u[dc*64 + dl] = sum_i q0s[i] * Wk[h*64+i][dc*64+dl]   (8 partitions x 8 i)
    const int part = t >> 6, dl = t & 63;
    {
        const float* base = Wk + (size_t)(h * 64 + part * 8) * Dd + dc * 64 + dl;
        float acc = 0.f;
        #pragma unroll
        for (int i = 0; i < 8; i++) acc += q0s[part * 8 + i] * base[(size_t)i * Dd];
        red8[part][dl] = acc;
    }
    __syncthreads();
    if (t < 64) {
        float u = 0.f;
        #pragma unroll
        for (int p = 0; p < 8; p++) u += red8[p][t];
        g_u[h][dc * 64 + t] = u;
        red64[t] = u * cts[dc * 64 + t];
    }
    __syncthreads();
    if (t < 32) {
        float v = red64[t] + red64[t + 32];
        v = warp_sum(v);
        if (t == 0) g_s0p[h][dc] = v;
        if (dc == 0) {   // ch = q0_h . bk_h
            float cvv = q0s[t] * bk[h * 64 + t] + q0s[t + 32] * bk[h * 64 + t + 32];
            cvv = warp_sum(cvv);
            if (t == 0) g_ch[h] = cvv;
        }
    }
}

// ============ k_main: fused scores + online softmax + weighted sum ============
// grid (NCH, B), 512 threads, dyn smem = 4 tile buffers (128 KB), all prefetched
__global__ void k_main(const float* __restrict__ nf, const float* __restrict__ masks) {
    extern __shared__ __align__(16) float dyn[];
    __shared__ __align__(16) float us[Hh][Dd];   // 16 KB
    __shared__ float sc[Hh][SUB], es[Hh][SUB];
    __shared__ float mh[Hh], sh[Hh], alpha[Hh], chs[Hh], msk[ROWS];
    const int c = blockIdx.x, b = blockIdx.y;
    const int t = threadIdx.x, wid = t >> 5, lane = t & 31;

    if (t < Hh) { mh[t] = -3e38f; sh[t] = 0.f; chs[t] = g_ch[t]; }
    if (t < ROWS) msk[t] = masks[(size_t)b * Nn + c * ROWS + t];
    {
        const float* uf = &g_u[0][0];
        #pragma unroll
        for (int k = 0; k < 8; k++) us[0][t + k * 512] = uf[t + k * 512];
    }
    // prefetch all 4 subtiles (max MLP)
    #pragma unroll
    for (int st = 0; st < NSUB; st++) {
        const float4* src = (const float4*)(nf + ((size_t)b * Nn + c * ROWS + st * SUB) * Dd);
        float4* dst = (float4*)(dyn + st * SUB * Dd);
        #pragma unroll
        for (int k = 0; k < 4; k++)
            __pipeline_memcpy_async(&dst[t + k * 512], &src[t + k * 512], 16);
        __pipeline_commit();
    }

    float z[Hh];
    #pragma unroll
    for (int h = 0; h < Hh; h++) z[h] = 0.f;

    #pragma unroll
    for (int st = 0; st < NSUB; st++) {
        __pipeline_wait_prior(NSUB - 1 - st);
        __syncthreads();
        const float* xt = dyn + st * SUB * Dd;
        // scores: warp w -> head w>>1, rows (w&1)*8..+8
        {
            const int h = wid >> 1, r0 = (wid & 1) * 8;
            const float4* uf4 = (const float4*)us[h];
            #pragma unroll
            for (int rr = 0; rr < 8; rr++) {
                const int r = r0 + rr;
                const float4* xf4 = (const float4*)(xt + r * Dd);
                float s = 0.f;
                #pragma unroll
                for (int k = 0; k < 4; k++) s += dot4(uf4[lane + 32 * k], xf4[lane + 32 * k]);
                s = warp_sum(s);
                if (lane == 0) {
                    float mv = msk[st * SUB + r];
                    float v = (s + chs[h]) * 0.125f;
                    if (mv * mv == 0.f) v = -1e9f;
                    sc[h][r] = v;
                }
            }
        }
        __syncthreads();
        if (wid < Hh) {   // online softmax per head
            const int h = wid;
            float v = (lane < SUB) ? sc[h][lane] : -3e38f;
            float m = warp_max(v);
            float mnew = fmaxf(mh[h], m);
            float e = (lane < SUB) ? expf(v - mnew) : 0.f;
            float ss = warp_sum(e);
            if (lane < SUB) es[h][lane] = e;
            if (lane == 0) {
                alpha[h] = expf(mh[h] - mnew);
                sh[h] = sh[h] * alpha[h] + ss;
                mh[h] = mnew;
            }
        }
        __syncthreads();
        #pragma unroll
        for (int h = 0; h < Hh; h++) z[h] *= alpha[h];
        #pragma unroll 4
        for (int r = 0; r < SUB; r++) {
            const float xv = xt[r * Dd + t];
            #pragma unroll
            for (int h = 0; h < Hh; h++) z[h] += es[h][r] * xv;
        }
    }
    __syncthreads();
    #pragma unroll
    for (int h = 0; h < Hh; h++) g_zp[c][b][h][t] = z[h];
    if (t < Hh) { g_pm[b][c][t] = mh[t]; g_ps[b][c][t] = sh[t]; }
}

// ============ k_rv: per (h,b): softmax combine + z reduce + Wv GEMV ============
// grid (Hh, Bx), 512 threads
__global__ void k_rv(const float* __restrict__ ct, const float* __restrict__ Wv,
                     const float* __restrict__ bv) {
    const int h = blockIdx.x, b = blockIdx.y;
    const int t = threadIdx.x, wid = t >> 5, lane = t & 31;
    __shared__ float f[NCH], Msh, Ssh, f0sh;
    __shared__ __align__(16) float zs[Dd];
    if (t < 32) {
        float sp = (lane < 8) ? g_s0p[h][lane] : 0.f;
        sp = warp_sum(sp);
        const float s0 = (sp + g_ch[h]) * 0.125f;
        const float pm = g_pm[b][lane][h];
        const float M = fmaxf(warp_max(pm), s0);
        float e = g_ps[b][lane][h] * expf(pm - M);
        e = warp_sum(e);
        const float S = e + expf(s0 - M);
        f[lane] = expf(pm - M) / S;
        if (lane == 0) { Msh = M; Ssh = S; f0sh = expf(s0 - M) / S; }
    }
    __syncthreads();
    // z[t] = f0*ct[t] + sum_c f[c]*zp[c][b][h][t]
    {
        float acc = f0sh * ct[t];
        #pragma unroll 8
        for (int c = 0; c < NCH; c++) acc += f[c] * g_zp[c][b][h][t];
        zs[t] = acc;
    }
    __syncthreads();
    // w[h*64+i] = bv + Wv row . z   (16 warps x 4 rows)
    const float4* zv = (const float4*)zs;
    #pragma unroll
    for (int rr = 0; rr < 4; rr++) {
        const int i = h * 64 + wid + rr * 16;
        const float4* row = (const float4*)(Wv + (size_t)i * Dd);
        float s = 0.f;
        #pragma unroll
        for (int k = 0; k < 4; k++) s += dot4(row[lane + 32 * k], zv[lane + 32 * k]);
        s = warp_sum(s);
        if (lane == 0) g_w[b][i] = s + bv[i];
    }
}

// ============ k_woln: y = Wo w + bo + ct (128 blocks), last block does LayerNorm ============
// grid 128, 256 threads
__global__ void k_woln(const float* __restrict__ Wo, const float* __restrict__ bo,
                       const float* __restrict__ ct, const float* __restrict__ gamma,
                       const float* __restrict__ beta, float* __restrict__ out) {
    const int t = threadIdx.x, wid = t >> 5, lane = t & 31;
    __shared__ __align__(16) float ws[Bx][Dd];
    __shared__ float part[4][2][Bx];
    __shared__ float red[256];
    __shared__ bool isLast;
    for (int idx = t; idx < Bx * Dd; idx += 256)
        ws[idx >> 9][idx & 511] = g_w[idx >> 9][idx & 511];
    __syncthreads();
    const int rloc = wid >> 1, half = wid & 1;
    const int r = blockIdx.x * 4 + rloc;
    const float4* row = (const float4*)(Wo + (size_t)r * Dd) + half * 64;
    float sb[Bx] = {0.f, 0.f, 0.f, 0.f};
    #pragma unroll
    for (int k = 0; k < 2; k++) {
        const float4 rv = row[lane + 32 * k];
        #pragma unroll
        for (int b = 0; b < Bx; b++)
            sb[b] += dot4(rv, ((const float4*)ws[b])[half * 64 + lane + 32 * k]);
    }
    #pragma unroll
    for (int b = 0; b < Bx; b++) {
        sb[b] = warp_sum(sb[b]);
        if (lane == 0) part[rloc][half][b] = sb[b];
    }
    __syncthreads();
    if (t < 16) {
        const int rl = t >> 2, b = t & 3;
        const int rr = blockIdx.x * 4 + rl;
        g_y[b][rr] = part[rl][0][b] + part[rl][1][b] + bo[rr] + ct[rr];
    }
    __syncthreads();
    if (t == 0) {
        __threadfence();
        unsigned v = atomicAdd(&g_cnt, 1u);
        isLast = (v == gridDim.x - 1);
    }
    __syncthreads();
    if (!isLast) return;
    __threadfence();
    // LayerNorm for all 4 batches (result independent of which block runs this)
    for (int b = 0; b < Bx; b++) {
        const float y0 = g_y[b][t], y1 = g_y[b][t + 256];
        red[t] = y0 + y1;
        __syncthreads();
        for (int o = 128; o; o >>= 1) { if (t < o) red[t] += red[t + o]; __syncthreads(); }
        const float mu = red[0] * (1.f / Dd);
        __syncthreads();
        const float d0 = y0 - mu, d1 = y1 - mu;
        red[t] = d0 * d0 + d1 * d1;
        __syncthreads();
        for (int o = 128; o; o >>= 1) { if (t < o) red[t] += red[t + o]; __syncthreads(); }
        const float rs = rsqrtf(red[0] * (1.f / Dd) + 1e-5f);
        out[(size_t)b * Dd + t]       = d0 * rs * gamma[t] + beta[t];
        out[(size_t)b * Dd + t + 256] = d1 * rs * gamma[t + 256] + beta[t + 256];
        __syncthreads();
    }
    if (t == 0) g_cnt = 0;   // reset for next graph replay
}

// ---------------- launcher ----------------
extern "C" void kernel_launch(void* const* d_in, const int* in_sizes, int n_in,
                              void* d_out, int out_size) {
    const float* nf    = (const float*)d_in[0];
    // d_in[1] edge_weights, d_in[2] adj_matrix: dead for CLS-row output
    const float* masks = (const float*)d_in[3];
    const float* ct    = (const float*)d_in[4];
    const float* Wq    = (const float*)d_in[5];
    const float* bq    = (const float*)d_in[6];
    const float* Wk    = (const float*)d_in[7];
    const float* bk    = (const float*)d_in[8];
    const float* Wv    = (const float*)d_in[9];
    const float* bv    = (const float*)d_in[10];
    const float* Wo    = (const float*)d_in[11];
    const float* bo    = (const float*)d_in[12];
    const float* gamma = (const float*)d_in[13];
    const float* beta  = (const float*)d_in[14];
    float* out = (float*)d_out;

    const int dyn = NSUB * SUB * Dd * sizeof(float);   // 128 KB
    static bool attr_set = false;
    if (!attr_set) {
        cudaFuncSetAttribute(k_main, cudaFuncAttributeMaxDynamicSharedMemorySize, dyn);
        attr_set = true;
    }

    k_prep<<<dim3(Hh, 8), 512>>>(Wq, bq, Wk, bk, ct);
    k_main<<<dim3(NCH, Bx), 512, dyn>>>(nf, masks);
    k_rv  <<<dim3(Hh, Bx), 512>>>(ct, Wv, bv);
    k_woln<<<128, 256>>>(Wo, bo, ct, gamma, beta, out);
}